// round 4
// baseline (speedup 1.0000x reference)
#include <cuda_runtime.h>
#include <cstdint>

#define N_ANCH   100800
#define D_COLS   117
#define NC       80
#define NM       32
#define TOPK     4096
#define MAX_DET  300
#define CONF_T   0.25f
#define IOU_T    0.45f
#define CAND_CAP 8192
#define NWORDS   128            // TOPK/32

// ---------------- scratch (static __device__ — no allocation) ----------------
__device__ float              g_score[N_ANCH];
__device__ float              g_cls[N_ANCH];
__device__ unsigned int       g_hist[65536];
__device__ unsigned int       g_thresh_bucket;
__device__ unsigned int       g_ncand;
__device__ unsigned long long g_cand[CAND_CAP];
__device__ int                g_top_idx[TOPK];
__device__ float              g_top_s[TOPK];
__device__ float              g_by1[TOPK], g_bx1[TOPK], g_by2[TOPK], g_bx2[TOPK], g_bar[TOPK];
// transposed suppression bitmask: g_maskT[jword*TOPK + row]
__device__ unsigned int       g_maskT[NWORDS * TOPK];
__device__ int                g_out_pos[MAX_DET];
__device__ unsigned char      g_out_keep[MAX_DET];

// ---------------- helpers ----------------
__device__ __forceinline__ unsigned int f2key(float f) {
    unsigned int b = __float_as_uint(f);
    return b ^ ((b >> 31) ? 0xFFFFFFFFu : 0x80000000u);
}
__device__ __forceinline__ float key2f(unsigned int k) {
    unsigned int b = (k & 0x80000000u) ? (k ^ 0x80000000u) : ~k;
    return __uint_as_float(b);
}

// ---------------- k0: zero hist + counter ----------------
__global__ void k_zero() {
    int i = blockIdx.x * blockDim.x + threadIdx.x;   // 65536 threads
    g_hist[i] = 0u;
    if (i == 0) g_ncand = 0u;
}

// ---------------- k1: per-anchor score/class + histogram (warp per anchor) ---
__global__ void k_score(const float* __restrict__ x) {
    int warp = (blockIdx.x * blockDim.x + threadIdx.x) >> 5;
    int lane = threadIdx.x & 31;
    if (warp >= N_ANCH) return;
    const float* row = x + (size_t)warp * D_COLS;
    float obj = row[4];

    float best = -1.0f; int bc = NC;
#pragma unroll
    for (int k = 0; k < 3; k++) {
        int c = lane + 32 * k;
        if (c < NC) {
            float v = __fmul_rn(row[5 + c], obj);
            if (v > best) { best = v; bc = c; }
        }
    }
#pragma unroll
    for (int off = 16; off; off >>= 1) {
        float ov = __shfl_down_sync(0xFFFFFFFFu, best, off);
        int   oc = __shfl_down_sync(0xFFFFFFFFu, bc,   off);
        if (ov > best || (ov == best && oc < bc)) { best = ov; bc = oc; }
    }
    if (lane == 0) {
        float s = (obj > CONF_T) ? best : -1.0f;
        g_score[warp] = s;
        g_cls[warp]   = (float)bc;
        atomicAdd(&g_hist[f2key(s) >> 16], 1u);
    }
}

// ---------------- k2: fused threshold-bucket search (one block) --------------
__global__ void __launch_bounds__(1024, 1) k_thresh() {
    __shared__ unsigned int part[64 * 32];   // [chunk][warp]
    __shared__ unsigned int chunk[64];
    __shared__ unsigned int suf[1024];
    __shared__ int          s_c;
    __shared__ unsigned int s_rem;
    int t = threadIdx.x, wid = t >> 5, lane = t & 31;

    // chunk sums: coalesced loads, warp-reduce, no atomics
    for (int c = 0; c < 64; c++) {
        unsigned int v = g_hist[c * 1024 + t];
#pragma unroll
        for (int off = 16; off; off >>= 1) v += __shfl_down_sync(0xFFFFFFFFu, v, off);
        if (lane == 0) part[c * 32 + wid] = v;
    }
    __syncthreads();
    if (t < 64) {
        unsigned int s = 0;
#pragma unroll 8
        for (int w = 0; w < 32; w++) s += part[t * 32 + w];
        chunk[t] = s;
    }
    __syncthreads();
    if (t == 0) {
        unsigned int cum = 0; int c = 0; unsigned int rem = TOPK;
        for (int b = 63; b >= 0; b--) {
            if (cum + chunk[b] >= TOPK) { c = b; rem = TOPK - cum; break; }
            cum += chunk[b];
        }
        s_c = c; s_rem = rem;
    }
    __syncthreads();
    int c = s_c;
    suf[t] = g_hist[c * 1024 + t];
    __syncthreads();
    for (int off = 1; off < 1024; off <<= 1) {
        unsigned int v = (t + off < 1024) ? suf[t + off] : 0u;
        __syncthreads();
        suf[t] += v;
        __syncthreads();
    }
    unsigned int rem = s_rem;
    if (suf[t] >= rem && (t == 1023 || suf[t + 1] < rem))
        g_thresh_bucket = (unsigned int)(c * 1024 + t);
}

// ---------------- k3: compact candidates ----------------
__global__ void k_compact() {
    int i = blockIdx.x * blockDim.x + threadIdx.x;
    if (i >= N_ANCH) return;
    unsigned int k = f2key(g_score[i]);
    if ((k >> 16) >= g_thresh_bucket) {
        unsigned int pos = atomicAdd(&g_ncand, 1u);
        if (pos < CAND_CAP)
            g_cand[pos] = ((unsigned long long)k << 32) | (unsigned int)(~i);
    }
}

// ---------------- k4: rank candidates -> sorted top-4096 (+ box gather) ------
__global__ void k_rank(const float* __restrict__ x) {
    __shared__ unsigned long long tile[256];
    int i = blockIdx.x * 256 + threadIdx.x;
    unsigned int n = g_ncand; if (n > CAND_CAP) n = CAND_CAP;
    unsigned long long my = (i < (int)n) ? g_cand[i] : 0ULL;
    int rank = 0;
    for (unsigned int base = 0; base < n; base += 256) {
        unsigned int idx = base + threadIdx.x;
        tile[threadIdx.x] = (idx < n) ? g_cand[idx] : 0ULL;
        __syncthreads();
        unsigned int lim = (n - base < 256u) ? (n - base) : 256u;
        for (unsigned int k = 0; k < lim; k++) rank += (tile[k] > my);
        __syncthreads();
    }
    if (i < (int)n && rank < TOPK) {
        int a = (int)(~(unsigned int)my);
        g_top_s[rank]   = key2f((unsigned int)(my >> 32));
        g_top_idx[rank] = a;
        const float* row = x + (size_t)a * D_COLS;
        float xc = row[0], yc = row[1], w = row[2], h = row[3];
        float hh = __fmul_rn(h, 0.5f), hw = __fmul_rn(w, 0.5f);
        float y1 = __fsub_rn(yc, hh), x1 = __fsub_rn(xc, hw);
        float y2 = __fadd_rn(yc, hh), x2 = __fadd_rn(xc, hw);
        g_by1[rank] = y1; g_bx1[rank] = x1; g_by2[rank] = y2; g_bx2[rank] = x2;
        g_bar[rank] = __fmul_rn(__fsub_rn(y2, y1), __fsub_rn(x2, x1));
    }
}

// ---------------- k5: dense suppression bitmask, transposed ------------------
// warp g=(rg,w): rows rg*32..+31 (lanes) vs cols w*32..+31; writes
// g_maskT[w*TOPK + i]. Lower triangle (w<rg) writes zeros -> no pre-clear.
__global__ void k_edges() {
    __shared__ float cy1[4][32], cx1[4][32], cy2[4][32], cx2[4][32], car[4][32];
    int wid  = threadIdx.x >> 5;
    int lane = threadIdx.x & 31;
    int g    = blockIdx.x * 4 + wid;
    int rg   = g >> 7;
    int w    = g & 127;
    int i    = (rg << 5) | lane;

    if (w < rg) { g_maskT[w * TOPK + i] = 0u; return; }

    int jj = (w << 5) + lane;
    cy1[wid][lane] = g_by1[jj]; cx1[wid][lane] = g_bx1[jj];
    cy2[wid][lane] = g_by2[jj]; cx2[wid][lane] = g_bx2[jj];
    car[wid][lane] = g_bar[jj];
    __syncwarp();

    float ry1 = g_by1[i], rx1 = g_bx1[i], ry2 = g_by2[i], rx2 = g_bx2[i];
    float rar = g_bar[i];
    bool  diag = (w == rg);

    unsigned int word = 0;
#pragma unroll 4
    for (int k = 0; k < 32; k++) {
        if (diag && k <= lane) continue;
        float yy1 = fmaxf(ry1, cy1[wid][k]);
        float xx1 = fmaxf(rx1, cx1[wid][k]);
        float yy2 = fminf(ry2, cy2[wid][k]);
        float xx2 = fminf(rx2, cx2[wid][k]);
        float dh  = fmaxf(__fsub_rn(yy2, yy1), 0.0f);
        float dw  = fmaxf(__fsub_rn(xx2, xx1), 0.0f);
        float it  = __fmul_rn(dh, dw);
        if (it > 0.0f) {
            float un  = __fsub_rn(__fadd_rn(rar, car[wid][k]), it);
            float unc = fmaxf(un, 1e-9f);
            float c   = __fmul_rn(IOU_T, unc);
            bool  sup;
            if (fabsf(__fsub_rn(it, c)) > 1e-4f * c) {
                sup = (it > c);                       // far from boundary
            } else {
                sup = (__fdiv_rn(it, unc) > IOU_T);   // exact ref rounding
            }
            if (sup) word |= 1u << k;
        }
    }
    g_maskT[w * TOPK + i] = word;
}

// ---------------- k6: greedy sweep, pipelined vector loads (128 thr) ---------
__global__ void __launch_bounds__(128, 1) k_resolve() {
    __shared__ unsigned int s_rm[NWORDS];
    __shared__ unsigned int s_kept;
    int t = threadIdx.x;

    unsigned int init_rm = 0;
#pragma unroll 4
    for (int b = 0; b < 32; b++)
        if (!(g_top_s[t * 32 + b] > -0.5f)) init_rm |= 1u << b;

    unsigned int acc = 0;
    const uint4* base = (const uint4*)(g_maskT + (size_t)t * TOPK);  // 1024 uint4

    uint4 A[8], B[8];
#pragma unroll
    for (int q = 0; q < 8; q++) A[q] = base[q];                      // w = 0

#define PROCESS(R, W)                                                          \
    do {                                                                       \
        const unsigned int* rw = (const unsigned int*)(R);                     \
        if (t == (W)) {                                                        \
            unsigned int rm = init_rm | acc;                                   \
            unsigned int kept = 0;                                             \
            _Pragma("unroll")                                                  \
            for (int b = 0; b < 32; b++) {                                     \
                if (!((rm >> b) & 1u)) { kept |= 1u << b; rm |= rw[b]; }       \
            }                                                                  \
            s_rm[(W)] = rm; s_kept = kept;                                     \
        }                                                                      \
        __syncthreads();                                                       \
        unsigned int kk = s_kept;                                              \
        _Pragma("unroll")                                                      \
        for (int b = 0; b < 32; b++)                                           \
            acc |= ((kk >> b) & 1u) ? rw[b] : 0u;                              \
        __syncthreads();                                                       \
    } while (0)

#pragma unroll 1
    for (int w = 0; w < NWORDS; w += 2) {
#pragma unroll
        for (int q = 0; q < 8; q++) B[q] = base[(w + 1) * 8 + q];    // prefetch w+1
        PROCESS(A, w);
        if (w + 2 < NWORDS) {
#pragma unroll
            for (int q = 0; q < 8; q++) A[q] = base[(w + 2) * 8 + q]; // prefetch w+2
        }
        PROCESS(B, w + 1);
    }
#undef PROCESS

    if (t == 0) {                  // top-300 positions: kept first, then pad
        int cnt = 0;
        for (int w = 0; w < NWORDS && cnt < MAX_DET; w++) {
            unsigned int alive = ~s_rm[w];
            while (alive && cnt < MAX_DET) {
                int b = __ffs(alive) - 1; alive &= alive - 1;
                g_out_pos[cnt] = (w << 5) | b; g_out_keep[cnt] = 1; cnt++;
            }
        }
        for (int w = 0; w < NWORDS && cnt < MAX_DET; w++) {
            unsigned int dead = s_rm[w];
            while (dead && cnt < MAX_DET) {
                int b = __ffs(dead) - 1; dead &= dead - 1;
                g_out_pos[cnt] = (w << 5) | b; g_out_keep[cnt] = 0; cnt++;
            }
        }
    }
}

// ---------------- k7: final gather -> d_out (warp per detection) -------------
__global__ void k_out(const float* __restrict__ x, float* __restrict__ out) {
    int warp = (blockIdx.x * blockDim.x + threadIdx.x) >> 5;
    int lane = threadIdx.x & 31;
    if (warp >= MAX_DET) return;
    int pos = g_out_pos[warp];
    int a   = g_top_idx[pos];
    const float* row = x + (size_t)a * D_COLS;
    if (lane == 0) {
        float xc = row[0], yc = row[1], w = row[2], h = row[3];
        float hh = __fmul_rn(h, 0.5f), hw = __fmul_rn(w, 0.5f);
        out[warp * 4 + 0] = __fsub_rn(yc, hh);
        out[warp * 4 + 1] = __fsub_rn(xc, hw);
        out[warp * 4 + 2] = __fadd_rn(yc, hh);
        out[warp * 4 + 3] = __fadd_rn(xc, hw);
        out[MAX_DET * 4 + warp] = g_cls[a];
        out[MAX_DET * 5 + warp] = g_out_keep[warp] ? g_top_s[pos] : -1.0f;
    }
    out[MAX_DET * 6 + warp * NM + lane] = row[5 + NC + lane];
}

// ---------------- launch ----------------
extern "C" void kernel_launch(void* const* d_in, const int* in_sizes, int n_in,
                              void* d_out, int out_size) {
    const float* x = (const float*)d_in[0];
    float* out = (float*)d_out;

    k_zero    <<<64, 1024>>>();
    k_score   <<<(N_ANCH * 32 + 255) / 256, 256>>>(x);
    k_thresh  <<<1, 1024>>>();
    k_compact <<<(N_ANCH + 255) / 256, 256>>>();
    k_rank    <<<CAND_CAP / 256, 256>>>(x);
    k_edges   <<<4096, 128>>>();
    k_resolve <<<1, 128>>>();
    k_out     <<<(MAX_DET * 32 + 255) / 256, 256>>>(x, out);
}